// round 11
// baseline (speedup 1.0000x reference)
#include <cuda_runtime.h>
#include <cuda_fp16.h>
#include <cstdint>

#define NN 100000
#define EE 800000
#define DD 128
#define TH0 0.5f
#define TH1 0.3f
#define TH2 0.2f
#define NEG 0.01f

// smem offsets (bytes)
#define OFFA 0
#define OFFB 32768
#define OFFLP 65536                     // float2[2][128] = 2048
#define OFFPS 67584                     // float[128]
#define PRED_SMEM (OFFPS + 512)
#define FIN_SMEM  65536

// ---------------- device scratch ----------------
__device__ int   g_deg[NN];
__device__ int   g_rowptr[NN + 1];
__device__ int   g_cursor[NN];
__device__ int   g_partials[128];
__device__ float g_dinv[NN];           // deg^-1/2
__device__ float g_rdeg[NN];           // deg^+1/2
__device__ int   g_col[EE];
__device__ __align__(16) __half g_xs0h[NN * DD];       // dinv*xk0 as f16
__device__ __align__(16) __half g_xs1h[NN * DD];       // dinv*xk1 as f16
__device__ __align__(16) __half g_hih[NN * DD];        // hi as f16
__device__ __align__(16) __half g_W1h[128 * 128];      // W1 [n][k] f16
__device__ __align__(16) __half g_Bh[128 * 384];       // combined B [n][kk] f16

// ---------------- helpers ----------------
__device__ __forceinline__ uint32_t smem_u32(const void* p) {
    uint32_t a;
    asm("{ .reg .u64 t; cvta.to.shared.u64 t, %1; cvt.u32.u64 %0, t; }" : "=r"(a) : "l"(p));
    return a;
}
__device__ __forceinline__ void ldsm4(uint32_t* r, uint32_t addr) {
    asm volatile("ldmatrix.sync.aligned.m8n8.x4.shared.b16 {%0,%1,%2,%3}, [%4];"
                 : "=r"(r[0]), "=r"(r[1]), "=r"(r[2]), "=r"(r[3]) : "r"(addr));
}
__device__ __forceinline__ void mma16816(float* c, const uint32_t* a, const uint32_t* b) {
    asm volatile("mma.sync.aligned.m16n8k16.row.col.f32.f16.f16.f32 "
                 "{%0,%1,%2,%3},{%4,%5,%6,%7},{%8,%9},{%0,%1,%2,%3};"
                 : "+f"(c[0]), "+f"(c[1]), "+f"(c[2]), "+f"(c[3])
                 : "r"(a[0]), "r"(a[1]), "r"(a[2]), "r"(a[3]), "r"(b[0]), "r"(b[1]));
}
__device__ __forceinline__ uint4 pack8(float4 a, float4 b) {
    __half2 h0 = __floats2half2_rn(a.x, a.y);
    __half2 h1 = __floats2half2_rn(a.z, a.w);
    __half2 h2 = __floats2half2_rn(b.x, b.y);
    __half2 h3 = __floats2half2_rn(b.z, b.w);
    return make_uint4(*(unsigned*)&h0, *(unsigned*)&h1, *(unsigned*)&h2, *(unsigned*)&h3);
}
__device__ __forceinline__ void unpack8(uint4 v, float* f) {
    float2 a = __half22float2(*(__half2*)&v.x);
    float2 b = __half22float2(*(__half2*)&v.y);
    float2 c = __half22float2(*(__half2*)&v.z);
    float2 d = __half22float2(*(__half2*)&v.w);
    f[0] = a.x; f[1] = a.y; f[2] = b.x; f[3] = b.y;
    f[4] = c.x; f[5] = c.y; f[6] = d.x; f[7] = d.y;
}
__device__ __forceinline__ uint4 pack8f(const float* f) {
    __half2 h0 = __floats2half2_rn(f[0], f[1]);
    __half2 h1 = __floats2half2_rn(f[2], f[3]);
    __half2 h2 = __floats2half2_rn(f[4], f[5]);
    __half2 h3 = __floats2half2_rn(f[6], f[7]);
    return make_uint4(*(unsigned*)&h0, *(unsigned*)&h1, *(unsigned*)&h2, *(unsigned*)&h3);
}
// smem byte address for (row, 16B-chunk) with XOR swizzle, 256B row stride
__device__ __forceinline__ int swz(int row, int chunk) {
    return row * 256 + ((chunk ^ (row & 7)) << 4);
}

// ---------------- prep: f16 operand images ----------------
__global__ void k_prep(const float* __restrict__ w1,
                       const float* __restrict__ lin_w,
                       const float* __restrict__ weights) {
    int bid = blockIdx.x, t = threadIdx.x;
    if (bid < 128) {
        g_W1h[bid * 128 + t] = __float2half_rn(w1[bid * 128 + t]);
    } else {
        int kk = bid - 128;            // 0..383
        float v;
        if (kk < 128) {
            v = lin_w[t * 256 + kk];
        } else {
            int r = kk - 128;
            float s = 0.f;
            #pragma unroll 4
            for (int o = 0; o < 128; o++)
                s = fmaf(__ldg(&weights[r * 128 + o]), __ldg(&lin_w[t * 256 + 128 + o]), s);
            v = s;
        }
        g_Bh[t * 384 + kk] = __float2half_rn(v);
    }
}

// ---------------- CSR build ----------------
__global__ void k_zero() {
    int i = blockIdx.x * blockDim.x + threadIdx.x;
    if (i < NN) g_deg[i] = 0;
}
__global__ void k_deg(const int* __restrict__ dst) {
    int i = blockIdx.x * blockDim.x + threadIdx.x;
    if (i < EE) atomicAdd(&g_deg[dst[i]], 1);
}
// block-level scan; also produces dinv/rdeg (deg is final here)
__global__ void k_scan_block() {
    __shared__ int s[1024];
    int i = blockIdx.x * 1024 + threadIdx.x;
    int v = (i < NN) ? g_deg[i] : 0;
    s[threadIdx.x] = v;
    __syncthreads();
    for (int off = 1; off < 1024; off <<= 1) {
        int t = (threadIdx.x >= off) ? s[threadIdx.x - off] : 0;
        __syncthreads();
        s[threadIdx.x] += t;
        __syncthreads();
    }
    if (i < NN) {
        g_rowptr[i] = s[threadIdx.x] - v;
        float df = (float)(v > 0 ? v : 1);
        g_dinv[i] = rsqrtf(df);
        g_rdeg[i] = sqrtf(df);
    }
    if (threadIdx.x == 1023) g_partials[blockIdx.x] = s[1023];
}
__global__ void k_scan_add() {
    __shared__ int s[128];
    int bid = blockIdx.x;
    if (threadIdx.x < 128)
        s[threadIdx.x] = (threadIdx.x < bid) ? g_partials[threadIdx.x] : 0;
    __syncthreads();
    #pragma unroll
    for (int off = 64; off > 0; off >>= 1) {
        if (threadIdx.x < off) s[threadIdx.x] += s[threadIdx.x + off];
        __syncthreads();
    }
    int soff = s[0];
    int i = bid * 1024 + threadIdx.x;
    if (i < NN) {
        int r = g_rowptr[i] + soff;
        g_rowptr[i] = r;
        g_cursor[i] = r;
        if (i == NN - 1) g_rowptr[NN] = EE;
    }
}
__global__ void k_fill(const int* __restrict__ src, const int* __restrict__ dst) {
    int i = blockIdx.x * blockDim.x + threadIdx.x;
    if (i < EE) {
        int p = atomicAdd(&g_cursor[dst[i]], 1);
        g_col[p] = src[i];
    }
}

// ---------------- predictor: HMMA GEMM + softmax head -> xs0h ----------------
__global__ __launch_bounds__(256)
void k_pred(const float* __restrict__ x, const float* __restrict__ b1,
            const float* __restrict__ w2, const float* __restrict__ b2,
            const float* __restrict__ alpha, const float* __restrict__ emb) {
    extern __shared__ __align__(16) unsigned char sm[];
    uint32_t sbase = smem_u32(sm);
    const int tid = threadIdx.x, lane = tid & 31, wid = tid >> 5;
    const int n0 = blockIdx.x * 128;
    const int rows = min(128, NN - n0);

    for (int i = tid; i < 2048; i += 256) {
        int r = i >> 4, c = i & 15;
        float4 va = make_float4(0.f, 0.f, 0.f, 0.f), vb = va;
        if (r < rows) {
            va = *(const float4*)&x[(n0 + r) * 128 + c * 8];
            vb = *(const float4*)&x[(n0 + r) * 128 + c * 8 + 4];
        }
        *(uint4*)(sm + OFFA + swz(r, c)) = pack8(va, vb);
    }
    for (int i = tid; i < 2048; i += 256) {
        int r = i >> 4, c = i & 15;
        *(uint4*)(sm + OFFB + swz(r, c)) = ((const uint4*)g_W1h)[i];
    }
    __syncthreads();

    const int wm = wid & 3, wn = wid >> 2;
    const int m_base = wm * 32, n_base = wn * 64;
    const int rA0 = m_base + (lane & 15), rA1 = rA0 + 16;
    const int chA = lane >> 4;
    int rB[4];
    #pragma unroll
    for (int np = 0; np < 4; np++)
        rB[np] = n_base + np * 16 + (lane & 7) + ((lane & 16) >> 1);
    const int chB = (lane >> 3) & 1;

    float acc[2][8][4];
    #pragma unroll
    for (int mt = 0; mt < 2; mt++)
        #pragma unroll
        for (int nt = 0; nt < 8; nt++)
            #pragma unroll
            for (int q = 0; q < 4; q++) acc[mt][nt][q] = 0.f;

    #pragma unroll
    for (int ks = 0; ks < 8; ks++) {
        uint32_t af[2][4], bf[4][4];
        ldsm4(af[0], sbase + OFFA + swz(rA0, 2 * ks + chA));
        ldsm4(af[1], sbase + OFFA + swz(rA1, 2 * ks + chA));
        #pragma unroll
        for (int np = 0; np < 4; np++)
            ldsm4(bf[np], sbase + OFFB + swz(rB[np], 2 * ks + chB));
        #pragma unroll
        for (int mt = 0; mt < 2; mt++)
            #pragma unroll
            for (int nt = 0; nt < 8; nt++)
                mma16816(acc[mt][nt], af[mt], &bf[nt >> 1][(nt & 1) * 2]);
    }
    __syncthreads();

    float lp0[2][2] = {{0.f, 0.f}, {0.f, 0.f}};
    float lp1[2][2] = {{0.f, 0.f}, {0.f, 0.f}};
    #pragma unroll
    for (int nt = 0; nt < 8; nt++) {
        int col = n_base + nt * 8 + 2 * (lane & 3);
        float b1a = __ldg(&b1[col]), b1b = __ldg(&b1[col + 1]);
        float wa0 = __ldg(&w2[col]), wb0 = __ldg(&w2[col + 1]);
        float wa1 = __ldg(&w2[128 + col]), wb1 = __ldg(&w2[128 + col + 1]);
        #pragma unroll
        for (int mt = 0; mt < 2; mt++)
            #pragma unroll
            for (int rh = 0; rh < 2; rh++) {
                float h0 = fmaxf(acc[mt][nt][2 * rh] + b1a, 0.f);
                float h1 = fmaxf(acc[mt][nt][2 * rh + 1] + b1b, 0.f);
                lp0[mt][rh] += h0 * wa0 + h1 * wb0;
                lp1[mt][rh] += h0 * wa1 + h1 * wb1;
            }
    }
    float2* Lp = (float2*)(sm + OFFLP);
    #pragma unroll
    for (int mt = 0; mt < 2; mt++)
        #pragma unroll
        for (int rh = 0; rh < 2; rh++) {
            float a0 = lp0[mt][rh], a1 = lp1[mt][rh];
            a0 += __shfl_xor_sync(0xFFFFFFFF, a0, 1);
            a0 += __shfl_xor_sync(0xFFFFFFFF, a0, 2);
            a1 += __shfl_xor_sync(0xFFFFFFFF, a1, 1);
            a1 += __shfl_xor_sync(0xFFFFFFFF, a1, 2);
            if ((lane & 3) == 0) {
                int row = m_base + mt * 16 + (lane >> 2) + rh * 8;
                Lp[wn * 128 + row] = make_float2(a0, a1);
            }
        }
    __syncthreads();

    float* Ps = (float*)(sm + OFFPS);
    if (tid < 128) {
        float2 u = Lp[tid], v = Lp[128 + tid];
        float l0 = u.x + v.x + __ldg(&b2[0]);
        float l1 = u.y + v.y + __ldg(&b2[1]);
        Ps[tid] = 1.f / (1.f + expf(l0 - l1));
    }
    __syncthreads();

    // epilogue: xs0 = (x + alpha*node)*dinv, reading x back from f16 smem tile
    const float al = __ldg(&alpha[0]);
    for (int idx = tid; idx < 128 * 16; idx += 256) {
        int m = idx >> 4, c = idx & 15;
        if (m < rows) {
            float p = Ps[m];
            float dv = __ldg(&g_dinv[n0 + m]);
            uint4 xv4 = *(uint4*)(sm + OFFA + swz(m, c));
            __half2* hp = (__half2*)&xv4;
            uint4 ov;
            unsigned* op = (unsigned*)&ov;
            #pragma unroll
            for (int j = 0; j < 4; j++) {
                float2 f = __half22float2(hp[j]);
                int cc = c * 8 + j * 2;
                float n0v = (1.f - p) * __ldg(&emb[cc])     + p * __ldg(&emb[128 + cc]);
                float n1v = (1.f - p) * __ldg(&emb[cc + 1]) + p * __ldg(&emb[128 + cc + 1]);
                __half2 h = __floats2half2_rn((f.x + al * n0v) * dv, (f.y + al * n1v) * dv);
                op[j] = *(unsigned*)&h;
            }
            ((uint4*)g_xs0h)[(n0 + m) * 16 + c] = ov;
        }
    }
}

// ---------------- Laplacian passes: 2 nodes/warp, 16 lanes x uint4 per row ----------------
__global__ __launch_bounds__(256)
void k_lap1() {
    int warp = (blockIdx.x * blockDim.x + threadIdx.x) >> 5;
    int lane = threadIdx.x & 31;
    int node = warp * 2 + (lane >> 4);
    if (node >= NN) return;
    int l = lane & 15;
    const uint4* xs = (const uint4*)g_xs0h;
    int beg = g_rowptr[node], end = g_rowptr[node + 1];
    float acc[8] = {0.f, 0.f, 0.f, 0.f, 0.f, 0.f, 0.f, 0.f};
    #pragma unroll 4
    for (int ei = beg; ei < end; ei++) {
        int u = __ldg(&g_col[ei]);
        float f[8];
        unpack8(__ldg(&xs[u * 16 + l]), f);
        #pragma unroll
        for (int j = 0; j < 8; j++) acc[j] += f[j];
    }
    float dv = g_dinv[node];
    float d2 = dv * dv;
    float xv[8];
    unpack8(xs[node * 16 + l], xv);
    float r[8];
    #pragma unroll
    for (int j = 0; j < 8; j++) r[j] = xv[j] - acc[j] * d2;
    ((uint4*)g_xs1h)[node * 16 + l] = pack8f(r);
}
// lap2 over node range [node0, node0+ncnt)
__global__ __launch_bounds__(256)
void k_lap2(int node0, int ncnt) {
    int warp = (blockIdx.x * blockDim.x + threadIdx.x) >> 5;
    int lane = threadIdx.x & 31;
    int node = node0 + warp * 2 + (lane >> 4);
    if (node >= node0 + ncnt || node >= NN) return;
    int l = lane & 15;
    const uint4* xs = (const uint4*)g_xs1h;
    int beg = g_rowptr[node], end = g_rowptr[node + 1];
    float acc[8] = {0.f, 0.f, 0.f, 0.f, 0.f, 0.f, 0.f, 0.f};
    #pragma unroll 4
    for (int ei = beg; ei < end; ei++) {
        int u = __ldg(&g_col[ei]);
        float f[8];
        unpack8(__ldg(&xs[u * 16 + l]), f);
        #pragma unroll
        for (int j = 0; j < 8; j++) acc[j] += f[j];
    }
    float dv = g_dinv[node];
    float rd = g_rdeg[node];
    float v0[8], v1[8];
    unpack8(((const uint4*)g_xs0h)[node * 16 + l], v0);
    unpack8(xs[node * 16 + l], v1);
    const float c1 = TH1 + TH2;
    float r[8];
    #pragma unroll
    for (int j = 0; j < 8; j++)
        r[j] = rd * (TH0 * v0[j] + c1 * v1[j]) - TH2 * (acc[j] * dv);
    ((uint4*)g_hih)[node * 16 + l] = pack8f(r);
}

// ---------------- final: HMMA GEMM (K=384, 3 segs) + leaky + x0; tile offset blk0 ----------------
__global__ __launch_bounds__(256)
void k_final(const float* __restrict__ e, const float* __restrict__ x,
             const float* __restrict__ x0, const float* __restrict__ linb,
             float* __restrict__ out, int blk0) {
    extern __shared__ __align__(16) unsigned char sm[];
    uint32_t sbase = smem_u32(sm);
    const int tid = threadIdx.x, lane = tid & 31, wid = tid >> 5;
    const int n0 = (blk0 + blockIdx.x) * 128;
    const int rows = min(128, NN - n0);

    const int wm = wid & 3, wn = wid >> 2;
    const int m_base = wm * 32, n_base = wn * 64;
    const int rA0 = m_base + (lane & 15), rA1 = rA0 + 16;
    const int chA = lane >> 4;
    int rB[4];
    #pragma unroll
    for (int np = 0; np < 4; np++)
        rB[np] = n_base + np * 16 + (lane & 7) + ((lane & 16) >> 1);
    const int chB = (lane >> 3) & 1;

    float acc[2][8][4];
    #pragma unroll
    for (int mt = 0; mt < 2; mt++)
        #pragma unroll
        for (int nt = 0; nt < 8; nt++)
            #pragma unroll
            for (int q = 0; q < 4; q++) acc[mt][nt][q] = 0.f;

    for (int s = 0; s < 3; s++) {
        if (s == 1) {
            for (int i = tid; i < 2048; i += 256) {
                int r = i >> 4, c = i & 15;
                uint4 v = make_uint4(0u, 0u, 0u, 0u);
                if (r < rows) v = ((const uint4*)g_hih)[(n0 + r) * 16 + c];
                *(uint4*)(sm + OFFA + swz(r, c)) = v;
            }
        } else {
            const float* srcm = (s == 0) ? e : x;
            for (int i = tid; i < 2048; i += 256) {
                int r = i >> 4, c = i & 15;
                float4 va = make_float4(0.f, 0.f, 0.f, 0.f), vb = va;
                if (r < rows) {
                    va = *(const float4*)&srcm[(n0 + r) * 128 + c * 8];
                    vb = *(const float4*)&srcm[(n0 + r) * 128 + c * 8 + 4];
                }
                *(uint4*)(sm + OFFA + swz(r, c)) = pack8(va, vb);
            }
        }
        for (int i = tid; i < 2048; i += 256) {
            int r = i >> 4, c = i & 15;
            *(uint4*)(sm + OFFB + swz(r, c)) = ((const uint4*)g_Bh)[r * 48 + s * 16 + c];
        }
        __syncthreads();

        #pragma unroll
        for (int ks = 0; ks < 8; ks++) {
            uint32_t af[2][4], bf[4][4];
            ldsm4(af[0], sbase + OFFA + swz(rA0, 2 * ks + chA));
            ldsm4(af[1], sbase + OFFA + swz(rA1, 2 * ks + chA));
            #pragma unroll
            for (int np = 0; np < 4; np++)
                ldsm4(bf[np], sbase + OFFB + swz(rB[np], 2 * ks + chB));
            #pragma unroll
            for (int mt = 0; mt < 2; mt++)
                #pragma unroll
                for (int nt = 0; nt < 8; nt++)
                    mma16816(acc[mt][nt], af[mt], &bf[nt >> 1][(nt & 1) * 2]);
        }
        __syncthreads();
    }

    #pragma unroll
    for (int mt = 0; mt < 2; mt++)
        #pragma unroll
        for (int rh = 0; rh < 2; rh++) {
            int row = m_base + mt * 16 + (lane >> 2) + rh * 8;
            if (row < rows) {
                int m = n0 + row;
                #pragma unroll
                for (int nt = 0; nt < 8; nt++) {
                    int col = n_base + nt * 8 + 2 * (lane & 3);
                    float v0 = acc[mt][nt][2 * rh]     + __ldg(&linb[col]);
                    float v1 = acc[mt][nt][2 * rh + 1] + __ldg(&linb[col + 1]);
                    v0 = v0 > 0.f ? v0 : NEG * v0;
                    v1 = v1 > 0.f ? v1 : NEG * v1;
                    float2 xb = *(const float2*)&x0[m * 128 + col];
                    *(float2*)&out[m * 128 + col] = make_float2(v0 + xb.x, v1 + xb.y);
                }
            }
        }
}

// ---------------- launcher (fork + lap2/final pipeline, serial fallback) ----------------
extern "C" void kernel_launch(void* const* d_in, const int* in_sizes, int n_in,
                              void* d_out, int out_size) {
    const int*   src     = (const int*)  d_in[0];
    const int*   dst     = (const int*)  d_in[1];
    const float* x0      = (const float*)d_in[2];
    const float* x       = (const float*)d_in[3];
    const float* e       = (const float*)d_in[4];
    const float* alpha   = (const float*)d_in[7];
    const float* emb     = (const float*)d_in[8];
    const float* w1      = (const float*)d_in[9];
    const float* b1      = (const float*)d_in[10];
    const float* w2      = (const float*)d_in[11];
    const float* b2      = (const float*)d_in[12];
    const float* weights = (const float*)d_in[13];
    const float* lin_w   = (const float*)d_in[14];
    const float* lin_b   = (const float*)d_in[15];
    float* out = (float*)d_out;

    static cudaStream_t sB = nullptr;
    static cudaEvent_t ev0 = nullptr, evD = nullptr, evP = nullptr;
    static cudaEvent_t evA = nullptr, evB = nullptr, evF = nullptr;
    static int tried = 0;
    if (!tried) {
        tried = 1;
        if (cudaStreamCreateWithFlags(&sB, cudaStreamNonBlocking) != cudaSuccess) { sB = nullptr; }
        if (sB) {
            if (cudaEventCreateWithFlags(&ev0, cudaEventDisableTiming) != cudaSuccess ||
                cudaEventCreateWithFlags(&evD, cudaEventDisableTiming) != cudaSuccess ||
                cudaEventCreateWithFlags(&evP, cudaEventDisableTiming) != cudaSuccess ||
                cudaEventCreateWithFlags(&evA, cudaEventDisableTiming) != cudaSuccess ||
                cudaEventCreateWithFlags(&evB, cudaEventDisableTiming) != cudaSuccess ||
                cudaEventCreateWithFlags(&evF, cudaEventDisableTiming) != cudaSuccess) {
                sB = nullptr;
            }
        }
    }

    cudaFuncSetAttribute(k_pred,  cudaFuncAttributeMaxDynamicSharedMemorySize, PRED_SMEM);
    cudaFuncSetAttribute(k_final, cudaFuncAttributeMaxDynamicSharedMemorySize, FIN_SMEM);

    const int NBLK_SCAN = (NN + 1023) / 1024;
    const int NBLK_GEMM = (NN + 127) / 128;           // 782
    const int NBLK_LAP  = ((NN + 1) / 2 * 32 + 255) / 256;

    // chunk split for the lap2/final pipeline: half the tiles each
    const int BLK_H0 = NBLK_GEMM / 2;                 // 391
    const int NODE_H = BLK_H0 * 128;                  // 50048
    const int LAPBLK_H0 = ((NODE_H + 1) / 2 * 32 + 255) / 256;
    const int NODE_R = NN - NODE_H;
    const int LAPBLK_H1 = ((NODE_R + 1) / 2 * 32 + 255) / 256;

    if (sB) {
        // fork side stream
        cudaEventRecord(ev0, 0);
        cudaStreamWaitEvent(sB, ev0, 0);

        // side stream: weight images
        k_prep<<<512, 128, 0, sB>>>(w1, lin_w, weights);

        // main stream: degree + scan (produces dinv/rdeg)
        k_zero<<<(NN + 255) / 256, 256>>>();
        k_deg<<<(EE + 255) / 256, 256>>>(dst);
        k_scan_block<<<NBLK_SCAN, 1024>>>();
        cudaEventRecord(evD, 0);

        // side stream: predictor GEMM (needs dinv + W1h)
        cudaStreamWaitEvent(sB, evD, 0);
        k_pred<<<NBLK_GEMM, 256, PRED_SMEM, sB>>>(x, b1, w2, b2, alpha, emb);
        cudaEventRecord(evP, sB);

        // main stream: finish CSR concurrently with k_pred
        k_scan_add<<<NBLK_SCAN, 1024>>>();
        k_fill<<<(EE + 255) / 256, 256>>>(src, dst);

        // join, then lap1 (full)
        cudaStreamWaitEvent(0, evP, 0);
        k_lap1<<<NBLK_LAP, 256>>>();

        // pipelined lap2 / k_final
        k_lap2<<<LAPBLK_H0, 256>>>(0, NODE_H);
        cudaEventRecord(evA, 0);
        k_lap2<<<LAPBLK_H1, 256>>>(NODE_H, NODE_R);
        cudaEventRecord(evB, 0);

        cudaStreamWaitEvent(sB, evA, 0);
        k_final<<<BLK_H0, 256, FIN_SMEM, sB>>>(e, x, x0, lin_b, out, 0);
        cudaStreamWaitEvent(sB, evB, 0);
        k_final<<<NBLK_GEMM - BLK_H0, 256, FIN_SMEM, sB>>>(e, x, x0, lin_b, out, BLK_H0);
        cudaEventRecord(evF, sB);
        cudaStreamWaitEvent(0, evF, 0);
    } else {
        // serial fallback on the legacy stream
        k_prep<<<512, 128>>>(w1, lin_w, weights);
        k_zero<<<(NN + 255) / 256, 256>>>();
        k_deg<<<(EE + 255) / 256, 256>>>(dst);
        k_scan_block<<<NBLK_SCAN, 1024>>>();
        k_pred<<<NBLK_GEMM, 256, PRED_SMEM>>>(x, b1, w2, b2, alpha, emb);
        k_scan_add<<<NBLK_SCAN, 1024>>>();
        k_fill<<<(EE + 255) / 256, 256>>>(src, dst);
        k_lap1<<<NBLK_LAP, 256>>>();
        k_lap2<<<((NN + 1) / 2 * 32 + 255) / 256, 256>>>(0, NN);
        k_final<<<NBLK_GEMM, 256, FIN_SMEM>>>(e, x, x0, lin_b, out, 0);
    }
}

// round 12
// speedup vs baseline: 1.0823x; 1.0823x over previous
#include <cuda_runtime.h>
#include <cuda_fp16.h>
#include <cstdint>

#define NN 100000
#define EE 800000
#define DD 128
#define TH0 0.5f
#define TH1 0.3f
#define TH2 0.2f
#define NEG 0.01f

// smem offsets (bytes)
#define OFFA 0
#define OFFB 32768
#define OFFLP 65536                     // float2[2][128] = 2048
#define OFFPS 67584                     // float[128]
#define PRED_SMEM (OFFPS + 512)
#define FIN_SMEM  65536

// ---------------- device scratch ----------------
__device__ int   g_deg[NN];
__device__ int   g_rowptr[NN + 1];
__device__ int   g_cursor[NN];
__device__ int   g_partials[128];
__device__ float g_dinv[NN];           // deg^-1/2
__device__ float g_rdeg[NN];           // deg^+1/2
__device__ int   g_col[EE];
__device__ __align__(16) __half g_xs0h[NN * DD];       // dinv*xk0 as f16
__device__ __align__(16) __half g_xs1h[NN * DD];       // dinv*xk1 as f16
__device__ __align__(16) __half g_hih[NN * DD];        // hi as f16
__device__ __align__(16) __half g_W1h[128 * 128];      // W1 [n][k] f16
__device__ __align__(16) __half g_Bh[128 * 384];       // combined B [n][kk] f16

// ---------------- helpers ----------------
__device__ __forceinline__ uint32_t smem_u32(const void* p) {
    uint32_t a;
    asm("{ .reg .u64 t; cvta.to.shared.u64 t, %1; cvt.u32.u64 %0, t; }" : "=r"(a) : "l"(p));
    return a;
}
__device__ __forceinline__ void ldsm4(uint32_t* r, uint32_t addr) {
    asm volatile("ldmatrix.sync.aligned.m8n8.x4.shared.b16 {%0,%1,%2,%3}, [%4];"
                 : "=r"(r[0]), "=r"(r[1]), "=r"(r[2]), "=r"(r[3]) : "r"(addr));
}
__device__ __forceinline__ void mma16816(float* c, const uint32_t* a, const uint32_t* b) {
    asm volatile("mma.sync.aligned.m16n8k16.row.col.f32.f16.f16.f32 "
                 "{%0,%1,%2,%3},{%4,%5,%6,%7},{%8,%9},{%0,%1,%2,%3};"
                 : "+f"(c[0]), "+f"(c[1]), "+f"(c[2]), "+f"(c[3])
                 : "r"(a[0]), "r"(a[1]), "r"(a[2]), "r"(a[3]), "r"(b[0]), "r"(b[1]));
}
__device__ __forceinline__ uint4 pack8(float4 a, float4 b) {
    __half2 h0 = __floats2half2_rn(a.x, a.y);
    __half2 h1 = __floats2half2_rn(a.z, a.w);
    __half2 h2 = __floats2half2_rn(b.x, b.y);
    __half2 h3 = __floats2half2_rn(b.z, b.w);
    return make_uint4(*(unsigned*)&h0, *(unsigned*)&h1, *(unsigned*)&h2, *(unsigned*)&h3);
}
__device__ __forceinline__ void unpack8(uint4 v, float* f) {
    float2 a = __half22float2(*(__half2*)&v.x);
    float2 b = __half22float2(*(__half2*)&v.y);
    float2 c = __half22float2(*(__half2*)&v.z);
    float2 d = __half22float2(*(__half2*)&v.w);
    f[0] = a.x; f[1] = a.y; f[2] = b.x; f[3] = b.y;
    f[4] = c.x; f[5] = c.y; f[6] = d.x; f[7] = d.y;
}
__device__ __forceinline__ uint4 pack8f(const float* f) {
    __half2 h0 = __floats2half2_rn(f[0], f[1]);
    __half2 h1 = __floats2half2_rn(f[2], f[3]);
    __half2 h2 = __floats2half2_rn(f[4], f[5]);
    __half2 h3 = __floats2half2_rn(f[6], f[7]);
    return make_uint4(*(unsigned*)&h0, *(unsigned*)&h1, *(unsigned*)&h2, *(unsigned*)&h3);
}
// smem byte address for (row, 16B-chunk) with XOR swizzle, 256B row stride
__device__ __forceinline__ int swz(int row, int chunk) {
    return row * 256 + ((chunk ^ (row & 7)) << 4);
}

// ---------------- prep: f16 operand images ----------------
__global__ void k_prep(const float* __restrict__ w1,
                       const float* __restrict__ lin_w,
                       const float* __restrict__ weights) {
    int bid = blockIdx.x, t = threadIdx.x;
    if (bid < 128) {
        g_W1h[bid * 128 + t] = __float2half_rn(w1[bid * 128 + t]);
    } else {
        int kk = bid - 128;            // 0..383
        float v;
        if (kk < 128) {
            v = lin_w[t * 256 + kk];
        } else {
            int r = kk - 128;
            float s = 0.f;
            #pragma unroll 4
            for (int o = 0; o < 128; o++)
                s = fmaf(__ldg(&weights[r * 128 + o]), __ldg(&lin_w[t * 256 + 128 + o]), s);
            v = s;
        }
        g_Bh[t * 384 + kk] = __float2half_rn(v);
    }
}

// ---------------- CSR build ----------------
__global__ void k_zero() {
    int i = blockIdx.x * blockDim.x + threadIdx.x;
    if (i < NN) g_deg[i] = 0;
}
__global__ void k_deg(const int* __restrict__ dst) {
    int i = blockIdx.x * blockDim.x + threadIdx.x;
    if (i < EE) atomicAdd(&g_deg[dst[i]], 1);
}
// block-level scan; also produces dinv/rdeg (deg is final here)
__global__ void k_scan_block() {
    __shared__ int s[1024];
    int i = blockIdx.x * 1024 + threadIdx.x;
    int v = (i < NN) ? g_deg[i] : 0;
    s[threadIdx.x] = v;
    __syncthreads();
    for (int off = 1; off < 1024; off <<= 1) {
        int t = (threadIdx.x >= off) ? s[threadIdx.x - off] : 0;
        __syncthreads();
        s[threadIdx.x] += t;
        __syncthreads();
    }
    if (i < NN) {
        g_rowptr[i] = s[threadIdx.x] - v;
        float df = (float)(v > 0 ? v : 1);
        g_dinv[i] = rsqrtf(df);
        g_rdeg[i] = sqrtf(df);
    }
    if (threadIdx.x == 1023) g_partials[blockIdx.x] = s[1023];
}
__global__ void k_scan_add() {
    __shared__ int s[128];
    int bid = blockIdx.x;
    if (threadIdx.x < 128)
        s[threadIdx.x] = (threadIdx.x < bid) ? g_partials[threadIdx.x] : 0;
    __syncthreads();
    #pragma unroll
    for (int off = 64; off > 0; off >>= 1) {
        if (threadIdx.x < off) s[threadIdx.x] += s[threadIdx.x + off];
        __syncthreads();
    }
    int soff = s[0];
    int i = bid * 1024 + threadIdx.x;
    if (i < NN) {
        int r = g_rowptr[i] + soff;
        g_rowptr[i] = r;
        g_cursor[i] = r;
        if (i == NN - 1) g_rowptr[NN] = EE;
    }
}
__global__ void k_fill(const int* __restrict__ src, const int* __restrict__ dst) {
    int i = blockIdx.x * blockDim.x + threadIdx.x;
    if (i < EE) {
        int p = atomicAdd(&g_cursor[dst[i]], 1);
        g_col[p] = src[i];
    }
}

// ---------------- predictor: HMMA GEMM + softmax head -> xs0h ----------------
__global__ __launch_bounds__(256)
void k_pred(const float* __restrict__ x, const float* __restrict__ b1,
            const float* __restrict__ w2, const float* __restrict__ b2,
            const float* __restrict__ alpha, const float* __restrict__ emb) {
    extern __shared__ __align__(16) unsigned char sm[];
    uint32_t sbase = smem_u32(sm);
    const int tid = threadIdx.x, lane = tid & 31, wid = tid >> 5;
    const int n0 = blockIdx.x * 128;
    const int rows = min(128, NN - n0);

    for (int i = tid; i < 2048; i += 256) {
        int r = i >> 4, c = i & 15;
        float4 va = make_float4(0.f, 0.f, 0.f, 0.f), vb = va;
        if (r < rows) {
            va = *(const float4*)&x[(n0 + r) * 128 + c * 8];
            vb = *(const float4*)&x[(n0 + r) * 128 + c * 8 + 4];
        }
        *(uint4*)(sm + OFFA + swz(r, c)) = pack8(va, vb);
    }
    for (int i = tid; i < 2048; i += 256) {
        int r = i >> 4, c = i & 15;
        *(uint4*)(sm + OFFB + swz(r, c)) = ((const uint4*)g_W1h)[i];
    }
    __syncthreads();

    const int wm = wid & 3, wn = wid >> 2;
    const int m_base = wm * 32, n_base = wn * 64;
    const int rA0 = m_base + (lane & 15), rA1 = rA0 + 16;
    const int chA = lane >> 4;
    int rB[4];
    #pragma unroll
    for (int np = 0; np < 4; np++)
        rB[np] = n_base + np * 16 + (lane & 7) + ((lane & 16) >> 1);
    const int chB = (lane >> 3) & 1;

    float acc[2][8][4];
    #pragma unroll
    for (int mt = 0; mt < 2; mt++)
        #pragma unroll
        for (int nt = 0; nt < 8; nt++)
            #pragma unroll
            for (int q = 0; q < 4; q++) acc[mt][nt][q] = 0.f;

    #pragma unroll
    for (int ks = 0; ks < 8; ks++) {
        uint32_t af[2][4], bf[4][4];
        ldsm4(af[0], sbase + OFFA + swz(rA0, 2 * ks + chA));
        ldsm4(af[1], sbase + OFFA + swz(rA1, 2 * ks + chA));
        #pragma unroll
        for (int np = 0; np < 4; np++)
            ldsm4(bf[np], sbase + OFFB + swz(rB[np], 2 * ks + chB));
        #pragma unroll
        for (int mt = 0; mt < 2; mt++)
            #pragma unroll
            for (int nt = 0; nt < 8; nt++)
                mma16816(acc[mt][nt], af[mt], &bf[nt >> 1][(nt & 1) * 2]);
    }
    __syncthreads();

    float lp0[2][2] = {{0.f, 0.f}, {0.f, 0.f}};
    float lp1[2][2] = {{0.f, 0.f}, {0.f, 0.f}};
    #pragma unroll
    for (int nt = 0; nt < 8; nt++) {
        int col = n_base + nt * 8 + 2 * (lane & 3);
        float b1a = __ldg(&b1[col]), b1b = __ldg(&b1[col + 1]);
        float wa0 = __ldg(&w2[col]), wb0 = __ldg(&w2[col + 1]);
        float wa1 = __ldg(&w2[128 + col]), wb1 = __ldg(&w2[128 + col + 1]);
        #pragma unroll
        for (int mt = 0; mt < 2; mt++)
            #pragma unroll
            for (int rh = 0; rh < 2; rh++) {
                float h0 = fmaxf(acc[mt][nt][2 * rh] + b1a, 0.f);
                float h1 = fmaxf(acc[mt][nt][2 * rh + 1] + b1b, 0.f);
                lp0[mt][rh] += h0 * wa0 + h1 * wb0;
                lp1[mt][rh] += h0 * wa1 + h1 * wb1;
            }
    }
    float2* Lp = (float2*)(sm + OFFLP);
    #pragma unroll
    for (int mt = 0; mt < 2; mt++)
        #pragma unroll
        for (int rh = 0; rh < 2; rh++) {
            float a0 = lp0[mt][rh], a1 = lp1[mt][rh];
            a0 += __shfl_xor_sync(0xFFFFFFFF, a0, 1);
            a0 += __shfl_xor_sync(0xFFFFFFFF, a0, 2);
            a1 += __shfl_xor_sync(0xFFFFFFFF, a1, 1);
            a1 += __shfl_xor_sync(0xFFFFFFFF, a1, 2);
            if ((lane & 3) == 0) {
                int row = m_base + mt * 16 + (lane >> 2) + rh * 8;
                Lp[wn * 128 + row] = make_float2(a0, a1);
            }
        }
    __syncthreads();

    float* Ps = (float*)(sm + OFFPS);
    if (tid < 128) {
        float2 u = Lp[tid], v = Lp[128 + tid];
        float l0 = u.x + v.x + __ldg(&b2[0]);
        float l1 = u.y + v.y + __ldg(&b2[1]);
        Ps[tid] = 1.f / (1.f + expf(l0 - l1));
    }
    __syncthreads();

    // epilogue: xs0 = (x + alpha*node)*dinv, reading x back from f16 smem tile
    const float al = __ldg(&alpha[0]);
    for (int idx = tid; idx < 128 * 16; idx += 256) {
        int m = idx >> 4, c = idx & 15;
        if (m < rows) {
            float p = Ps[m];
            float dv = __ldg(&g_dinv[n0 + m]);
            uint4 xv4 = *(uint4*)(sm + OFFA + swz(m, c));
            __half2* hp = (__half2*)&xv4;
            uint4 ov;
            unsigned* op = (unsigned*)&ov;
            #pragma unroll
            for (int j = 0; j < 4; j++) {
                float2 f = __half22float2(hp[j]);
                int cc = c * 8 + j * 2;
                float n0v = (1.f - p) * __ldg(&emb[cc])     + p * __ldg(&emb[128 + cc]);
                float n1v = (1.f - p) * __ldg(&emb[cc + 1]) + p * __ldg(&emb[128 + cc + 1]);
                __half2 h = __floats2half2_rn((f.x + al * n0v) * dv, (f.y + al * n1v) * dv);
                op[j] = *(unsigned*)&h;
            }
            ((uint4*)g_xs0h)[(n0 + m) * 16 + c] = ov;
        }
    }
}

// ---------------- Laplacian passes: 4 nodes/warp, 8 lanes x 2 uint4 per row ----------------
__global__ __launch_bounds__(256)
void k_lap1() {
    int warp = (blockIdx.x * blockDim.x + threadIdx.x) >> 5;
    int lane = threadIdx.x & 31;
    int node = warp * 4 + (lane >> 3);
    if (node >= NN) return;
    int l = lane & 7;
    const uint4* xs = (const uint4*)g_xs0h;
    int beg = g_rowptr[node], end = g_rowptr[node + 1];
    float acc[16];
    #pragma unroll
    for (int j = 0; j < 16; j++) acc[j] = 0.f;
    #pragma unroll 2
    for (int ei = beg; ei < end; ei++) {
        int u = __ldg(&g_col[ei]);
        uint4 a = __ldg(&xs[u * 16 + l]);
        uint4 b = __ldg(&xs[u * 16 + l + 8]);
        float fa[8], fb[8];
        unpack8(a, fa);
        unpack8(b, fb);
        #pragma unroll
        for (int j = 0; j < 8; j++) { acc[j] += fa[j]; acc[8 + j] += fb[j]; }
    }
    float dv = g_dinv[node];
    float d2 = dv * dv;
    float xv[8], r[8];
    unpack8(xs[node * 16 + l], xv);
    #pragma unroll
    for (int j = 0; j < 8; j++) r[j] = xv[j] - acc[j] * d2;
    ((uint4*)g_xs1h)[node * 16 + l] = pack8f(r);
    unpack8(xs[node * 16 + l + 8], xv);
    #pragma unroll
    for (int j = 0; j < 8; j++) r[j] = xv[j] - acc[8 + j] * d2;
    ((uint4*)g_xs1h)[node * 16 + l + 8] = pack8f(r);
}
__global__ __launch_bounds__(256)
void k_lap2() {
    int warp = (blockIdx.x * blockDim.x + threadIdx.x) >> 5;
    int lane = threadIdx.x & 31;
    int node = warp * 4 + (lane >> 3);
    if (node >= NN) return;
    int l = lane & 7;
    const uint4* xs = (const uint4*)g_xs1h;
    int beg = g_rowptr[node], end = g_rowptr[node + 1];
    float acc[16];
    #pragma unroll
    for (int j = 0; j < 16; j++) acc[j] = 0.f;
    #pragma unroll 2
    for (int ei = beg; ei < end; ei++) {
        int u = __ldg(&g_col[ei]);
        uint4 a = __ldg(&xs[u * 16 + l]);
        uint4 b = __ldg(&xs[u * 16 + l + 8]);
        float fa[8], fb[8];
        unpack8(a, fa);
        unpack8(b, fb);
        #pragma unroll
        for (int j = 0; j < 8; j++) { acc[j] += fa[j]; acc[8 + j] += fb[j]; }
    }
    float dv = g_dinv[node];
    float rd = g_rdeg[node];
    const float c1 = TH1 + TH2;
    float v0[8], v1[8], r[8];
    unpack8(((const uint4*)g_xs0h)[node * 16 + l], v0);
    unpack8(xs[node * 16 + l], v1);
    #pragma unroll
    for (int j = 0; j < 8; j++)
        r[j] = rd * (TH0 * v0[j] + c1 * v1[j]) - TH2 * (acc[j] * dv);
    ((uint4*)g_hih)[node * 16 + l] = pack8f(r);
    unpack8(((const uint4*)g_xs0h)[node * 16 + l + 8], v0);
    unpack8(xs[node * 16 + l + 8], v1);
    #pragma unroll
    for (int j = 0; j < 8; j++)
        r[j] = rd * (TH0 * v0[j] + c1 * v1[j]) - TH2 * (acc[8 + j] * dv);
    ((uint4*)g_hih)[node * 16 + l + 8] = pack8f(r);
}

// ---------------- final: HMMA GEMM (K=384, 3 segs) + leaky + x0 ----------------
__global__ __launch_bounds__(256)
void k_final(const float* __restrict__ e, const float* __restrict__ x,
             const float* __restrict__ x0, const float* __restrict__ linb,
             float* __restrict__ out) {
    extern __shared__ __align__(16) unsigned char sm[];
    uint32_t sbase = smem_u32(sm);
    const int tid = threadIdx.x, lane = tid & 31, wid = tid >> 5;
    const int n0 = blockIdx.x * 128;
    const int rows = min(128, NN - n0);

    const int wm = wid & 3, wn = wid >> 2;
    const int m_base = wm * 32, n_base = wn * 64;
    const int rA0 = m_base + (lane & 15), rA1 = rA0 + 16;
    const int chA = lane >> 4;
    int rB[4];
    #pragma unroll
    for (int np = 0; np < 4; np++)
        rB[np] = n_base + np * 16 + (lane & 7) + ((lane & 16) >> 1);
    const int chB = (lane >> 3) & 1;

    float acc[2][8][4];
    #pragma unroll
    for (int mt = 0; mt < 2; mt++)
        #pragma unroll
        for (int nt = 0; nt < 8; nt++)
            #pragma unroll
            for (int q = 0; q < 4; q++) acc[mt][nt][q] = 0.f;

    for (int s = 0; s < 3; s++) {
        if (s == 1) {
            for (int i = tid; i < 2048; i += 256) {
                int r = i >> 4, c = i & 15;
                uint4 v = make_uint4(0u, 0u, 0u, 0u);
                if (r < rows) v = ((const uint4*)g_hih)[(n0 + r) * 16 + c];
                *(uint4*)(sm + OFFA + swz(r, c)) = v;
            }
        } else {
            const float* srcm = (s == 0) ? e : x;
            for (int i = tid; i < 2048; i += 256) {
                int r = i >> 4, c = i & 15;
                float4 va = make_float4(0.f, 0.f, 0.f, 0.f), vb = va;
                if (r < rows) {
                    va = *(const float4*)&srcm[(n0 + r) * 128 + c * 8];
                    vb = *(const float4*)&srcm[(n0 + r) * 128 + c * 8 + 4];
                }
                *(uint4*)(sm + OFFA + swz(r, c)) = pack8(va, vb);
            }
        }
        for (int i = tid; i < 2048; i += 256) {
            int r = i >> 4, c = i & 15;
            *(uint4*)(sm + OFFB + swz(r, c)) = ((const uint4*)g_Bh)[r * 48 + s * 16 + c];
        }
        __syncthreads();

        #pragma unroll
        for (int ks = 0; ks < 8; ks++) {
            uint32_t af[2][4], bf[4][4];
            ldsm4(af[0], sbase + OFFA + swz(rA0, 2 * ks + chA));
            ldsm4(af[1], sbase + OFFA + swz(rA1, 2 * ks + chA));
            #pragma unroll
            for (int np = 0; np < 4; np++)
                ldsm4(bf[np], sbase + OFFB + swz(rB[np], 2 * ks + chB));
            #pragma unroll
            for (int mt = 0; mt < 2; mt++)
                #pragma unroll
                for (int nt = 0; nt < 8; nt++)
                    mma16816(acc[mt][nt], af[mt], &bf[nt >> 1][(nt & 1) * 2]);
        }
        __syncthreads();
    }

    #pragma unroll
    for (int mt = 0; mt < 2; mt++)
        #pragma unroll
        for (int rh = 0; rh < 2; rh++) {
            int row = m_base + mt * 16 + (lane >> 2) + rh * 8;
            if (row < rows) {
                int m = n0 + row;
                #pragma unroll
                for (int nt = 0; nt < 8; nt++) {
                    int col = n_base + nt * 8 + 2 * (lane & 3);
                    float v0 = acc[mt][nt][2 * rh]     + __ldg(&linb[col]);
                    float v1 = acc[mt][nt][2 * rh + 1] + __ldg(&linb[col + 1]);
                    v0 = v0 > 0.f ? v0 : NEG * v0;
                    v1 = v1 > 0.f ? v1 : NEG * v1;
                    float2 xb = *(const float2*)&x0[m * 128 + col];
                    *(float2*)&out[m * 128 + col] = make_float2(v0 + xb.x, v1 + xb.y);
                }
            }
        }
}

// ---------------- launcher (round-10 fork structure, serial fallback) ----------------
extern "C" void kernel_launch(void* const* d_in, const int* in_sizes, int n_in,
                              void* d_out, int out_size) {
    const int*   src     = (const int*)  d_in[0];
    const int*   dst     = (const int*)  d_in[1];
    const float* x0      = (const float*)d_in[2];
    const float* x       = (const float*)d_in[3];
    const float* e       = (const float*)d_in[4];
    const float* alpha   = (const float*)d_in[7];
    const float* emb     = (const float*)d_in[8];
    const float* w1      = (const float*)d_in[9];
    const float* b1      = (const float*)d_in[10];
    const float* w2      = (const float*)d_in[11];
    const float* b2      = (const float*)d_in[12];
    const float* weights = (const float*)d_in[13];
    const float* lin_w   = (const float*)d_in[14];
    const float* lin_b   = (const float*)d_in[15];
    float* out = (float*)d_out;

    static cudaStream_t sB = nullptr;
    static cudaEvent_t ev0 = nullptr, evD = nullptr, evP = nullptr;
    static int tried = 0;
    if (!tried) {
        tried = 1;
        if (cudaStreamCreateWithFlags(&sB, cudaStreamNonBlocking) != cudaSuccess) { sB = nullptr; }
        if (sB) {
            if (cudaEventCreateWithFlags(&ev0, cudaEventDisableTiming) != cudaSuccess ||
                cudaEventCreateWithFlags(&evD, cudaEventDisableTiming) != cudaSuccess ||
                cudaEventCreateWithFlags(&evP, cudaEventDisableTiming) != cudaSuccess) {
                sB = nullptr;
            }
        }
    }

    cudaFuncSetAttribute(k_pred,  cudaFuncAttributeMaxDynamicSharedMemorySize, PRED_SMEM);
    cudaFuncSetAttribute(k_final, cudaFuncAttributeMaxDynamicSharedMemorySize, FIN_SMEM);

    const int NBLK_SCAN = (NN + 1023) / 1024;
    const int NBLK_GEMM = (NN + 127) / 128;
    const int NBLK_LAP  = ((NN + 3) / 4 * 32 + 255) / 256;   // 4 nodes/warp

    if (sB) {
        // fork side stream
        cudaEventRecord(ev0, 0);
        cudaStreamWaitEvent(sB, ev0, 0);

        // side stream: weight images
        k_prep<<<512, 128, 0, sB>>>(w1, lin_w, weights);

        // main stream: degree + scan (produces dinv/rdeg)
        k_zero<<<(NN + 255) / 256, 256>>>();
        k_deg<<<(EE + 255) / 256, 256>>>(dst);
        k_scan_block<<<NBLK_SCAN, 1024>>>();
        cudaEventRecord(evD, 0);

        // side stream: predictor GEMM (needs dinv + W1h)
        cudaStreamWaitEvent(sB, evD, 0);
        k_pred<<<NBLK_GEMM, 256, PRED_SMEM, sB>>>(x, b1, w2, b2, alpha, emb);
        cudaEventRecord(evP, sB);

        // main stream: finish CSR concurrently with k_pred
        k_scan_add<<<NBLK_SCAN, 1024>>>();
        k_fill<<<(EE + 255) / 256, 256>>>(src, dst);

        // join, then laps + final
        cudaStreamWaitEvent(0, evP, 0);
    } else {
        // serial fallback on the legacy stream
        k_prep<<<512, 128>>>(w1, lin_w, weights);
        k_zero<<<(NN + 255) / 256, 256>>>();
        k_deg<<<(EE + 255) / 256, 256>>>(dst);
        k_scan_block<<<NBLK_SCAN, 1024>>>();
        k_pred<<<NBLK_GEMM, 256, PRED_SMEM>>>(x, b1, w2, b2, alpha, emb);
        k_scan_add<<<NBLK_SCAN, 1024>>>();
        k_fill<<<(EE + 255) / 256, 256>>>(src, dst);
    }
    k_lap1<<<NBLK_LAP, 256>>>();
    k_lap2<<<NBLK_LAP, 256>>>();
    k_final<<<NBLK_GEMM, 256, FIN_SMEM>>>(e, x, x0, lin_b, out);
}